// round 3
// baseline (speedup 1.0000x reference)
#include <cuda_runtime.h>
#include <cuda_fp16.h>
#include <math.h>

#define NHEADS   12
#define NLH      24          // (latent, head) pairs
#define CHSTRIDE 131072      // elems between channels within a (b,head) plane
#define PLANE    393216      // elems per (b,head) plane = 3*CHSTRIDE
#define LATELEMS 37748736    // elems per latent
#define NPIX_D   1048576.0   // pixels per head (8 * 131072)
#define GROUPS8  131072      // 8-pixel groups per (latent,head)
#define NB0      128         // blocks per (l,h) for pass0
#define NBS      128         // blocks per (l,h) for fp16 moments passes
#define NB4      256         // blocks per head for loss pass
#define BN_EPS   1e-5

// ---------------- device scratch (no allocation allowed) ----------------
__device__ __align__(16) __half d_x16[2][LATELEMS];   // fp16 staged latents (151MB)
__device__ float  d_part[3][NLH][NBS > NB0 ? NBS : NB0][9];  // per-block moment partials
__device__ float  d_lpart[NHEADS][NB4];                      // per-block loss partials
__device__ float  d_Af[3][NLH][9];
__device__ float  d_cf[3][NLH][3];
__device__ float  d_qf[NLH][3];
__device__ float  d_rf[NLH];

// ---------------- helpers ----------------
__device__ __forceinline__ void affine_relu(const float* A, const float* c,
                                            float& x0, float& x1, float& x2) {
  float y0 = fmaf(A[0], x0, fmaf(A[1], x1, fmaf(A[2], x2, c[0])));
  float y1 = fmaf(A[3], x0, fmaf(A[4], x1, fmaf(A[5], x2, c[1])));
  float y2 = fmaf(A[6], x0, fmaf(A[7], x1, fmaf(A[8], x2, c[2])));
  x0 = fmaxf(y0, 0.f); x1 = fmaxf(y1, 0.f); x2 = fmaxf(y2, 0.f);
}

__device__ __forceinline__ void mom_acc(float* s, float x0, float x1, float x2) {
  s[0] += x0; s[1] += x1; s[2] += x2;
  s[3] = fmaf(x0, x0, s[3]); s[4] = fmaf(x0, x1, s[4]); s[5] = fmaf(x0, x2, s[5]);
  s[6] = fmaf(x1, x1, s[6]); s[7] = fmaf(x1, x2, s[7]); s[8] = fmaf(x2, x2, s[8]);
}

__device__ __forceinline__ void block_write9(float* s, int stage, int lh, int bx) {
  #pragma unroll
  for (int k = 0; k < 9; k++)
    #pragma unroll
    for (int o = 16; o > 0; o >>= 1) s[k] += __shfl_down_sync(0xffffffffu, s[k], o);
  __shared__ float red[8][9];
  int warp = threadIdx.x >> 5, lane = threadIdx.x & 31;
  if (lane == 0) {
    #pragma unroll
    for (int k = 0; k < 9; k++) red[warp][k] = s[k];
  }
  __syncthreads();
  if (threadIdx.x < 9) {
    float t = 0.f;
    #pragma unroll
    for (int w = 0; w < 8; w++) t += red[w][threadIdx.x];
    d_part[stage][lh][bx][threadIdx.x] = t;
  }
}

union Pk { uint4 u; __half2 h[4]; };

// ---------------- pass 0: fp32 read -> moments of x + fp16 stage-out ----------------
__global__ void __launch_bounds__(256) pass0_kernel(const float* __restrict__ lat1,
                                                    const float* __restrict__ lat2) {
  int lh = blockIdx.y;
  int l = lh / NHEADS, head = lh - l * NHEADS;
  const float* __restrict__ src = l ? lat2 : lat1;
  __half* __restrict__ dst = d_x16[l];

  float s[9];
  #pragma unroll
  for (int k = 0; k < 9; k++) s[k] = 0.f;

  const int GPB = GROUPS8 / NB0;         // 1024
  const int ITER = GPB / 256;            // 4
  int base_g = blockIdx.x * GPB;

  for (int it = 0; it < ITER; it++) {
    int g  = base_g + it * 256 + threadIdx.x;
    int b  = g >> 14;                    // 16384 groups of 8 per channel
    int pg = (g & 16383) << 3;
    size_t po = (size_t)(b * NHEADS + head) * PLANE;
    const float* plane = src + po;
    Pk pk[3];
    #pragma unroll
    for (int c = 0; c < 3; c++) {
      float4 v0 = *(const float4*)(plane + c * CHSTRIDE + pg);
      float4 v1 = *(const float4*)(plane + c * CHSTRIDE + pg + 4);
      pk[c].h[0] = __floats2half2_rn(v0.x, v0.y);
      pk[c].h[1] = __floats2half2_rn(v0.z, v0.w);
      pk[c].h[2] = __floats2half2_rn(v1.x, v1.y);
      pk[c].h[3] = __floats2half2_rn(v1.z, v1.w);
      *(uint4*)(dst + po + c * CHSTRIDE + pg) = pk[c].u;
    }
    // accumulate moments of the *rounded* values (consistent with later passes)
    #pragma unroll
    for (int w = 0; w < 4; w++) {
      float2 f0 = __half22float2(pk[0].h[w]);
      float2 f1 = __half22float2(pk[1].h[w]);
      float2 f2 = __half22float2(pk[2].h[w]);
      mom_acc(s, f0.x, f1.x, f2.x);
      mom_acc(s, f0.y, f1.y, f2.y);
    }
  }
  block_write9(s, 0, lh, blockIdx.x);
}

// ---------------- fp16 moments passes (stage 1: h1, stage 2: h2) ----------------
// REV flips the (lh, block) traversal so this pass starts on the data the
// previous pass touched last (still L2-resident) -> zig-zag L2 reuse.
template <int S, bool REV>
__global__ void __launch_bounds__(256) momentsH_kernel() {
  int bid = blockIdx.y * NBS + blockIdx.x;
  if (REV) bid = NBS * NLH - 1 - bid;
  int lh = bid / NBS, bx = bid % NBS;
  const __half* __restrict__ src = d_x16[lh / NHEADS];
  int head = lh % NHEADS;

  float A1[9], c1[3], A2[9], c2[3];
  #pragma unroll
  for (int k = 0; k < 9; k++) A1[k] = d_Af[0][lh][k];
  #pragma unroll
  for (int k = 0; k < 3; k++) c1[k] = d_cf[0][lh][k];
  if (S >= 2) {
    #pragma unroll
    for (int k = 0; k < 9; k++) A2[k] = d_Af[1][lh][k];
    #pragma unroll
    for (int k = 0; k < 3; k++) c2[k] = d_cf[1][lh][k];
  }

  float s[9];
  #pragma unroll
  for (int k = 0; k < 9; k++) s[k] = 0.f;

  const int GPB = GROUPS8 / NBS;         // 1024
  const int ITER = GPB / 256;            // 4
  int base_g = bx * GPB;

  for (int it = 0; it < ITER; it++) {
    int g  = base_g + it * 256 + threadIdx.x;
    int b  = g >> 14;
    int pg = (g & 16383) << 3;
    size_t po = (size_t)(b * NHEADS + head) * PLANE;
    Pk pk[3];
    #pragma unroll
    for (int c = 0; c < 3; c++) pk[c].u = *(const uint4*)(src + po + c * CHSTRIDE + pg);
    #pragma unroll
    for (int w = 0; w < 4; w++) {
      float2 f0 = __half22float2(pk[0].h[w]);
      float2 f1 = __half22float2(pk[1].h[w]);
      float2 f2 = __half22float2(pk[2].h[w]);
      #pragma unroll
      for (int half = 0; half < 2; half++) {
        float x0 = half ? f0.y : f0.x;
        float x1 = half ? f1.y : f1.x;
        float x2 = half ? f2.y : f2.x;
        affine_relu(A1, c1, x0, x1, x2);
        if (S >= 2) affine_relu(A2, c2, x0, x1, x2);
        mom_acc(s, x0, x1, x2);
      }
    }
  }
  block_write9(s, S, lh, bx);
}

// ---------------- finalize: reduce partials, fold conv+BN into affine ----------------
template <int S, int NB>
__global__ void finalize_kernel(const float* __restrict__ W, const float* __restrict__ bb,
                                const float* __restrict__ g, const float* __restrict__ be,
                                const float* __restrict__ W4, const float* __restrict__ b4,
                                const float* __restrict__ g4, const float* __restrict__ be4) {
  int lh = threadIdx.x;
  if (lh >= NLH) return;
  int head = lh % NHEADS;
  double M[9];
  #pragma unroll
  for (int k = 0; k < 9; k++) M[k] = 0.0;
  for (int p = 0; p < NB; p++)
    #pragma unroll
    for (int k = 0; k < 9; k++) M[k] += (double)d_part[S][lh][p][k];

  const double inv = 1.0 / NPIX_D;
  double m[3], E[3][3];
  m[0] = M[0] * inv; m[1] = M[1] * inv; m[2] = M[2] * inv;
  E[0][0] = M[3] * inv; E[0][1] = E[1][0] = M[4] * inv; E[0][2] = E[2][0] = M[5] * inv;
  E[1][1] = M[6] * inv; E[1][2] = E[2][1] = M[7] * inv; E[2][2] = M[8] * inv;

  double Wl[3][3], bl[3];
  for (int o = 0; o < 3; o++) {
    for (int c = 0; c < 3; c++) Wl[o][c] = (double)W[head * 9 + o * 3 + c];
    bl[o] = (double)bb[head * 3 + o];
  }

  double Ad[3][3], cd[3];
  for (int o = 0; o < 3; o++) {
    double wm = Wl[o][0] * m[0] + Wl[o][1] * m[1] + Wl[o][2] * m[2];
    double mo = wm + bl[o];
    double e2 = 0.0;
    for (int c = 0; c < 3; c++)
      for (int d = 0; d < 3; d++) e2 += Wl[o][c] * Wl[o][d] * E[c][d];
    e2 += 2.0 * bl[o] * wm + bl[o] * bl[o];
    double v = e2 - mo * mo;
    double sc = (double)g[head * 3 + o] / sqrt(v + BN_EPS);
    for (int c = 0; c < 3; c++) Ad[o][c] = sc * Wl[o][c];
    cd[o] = sc * (bl[o] - mo) + (double)be[head * 3 + o];
  }
  for (int o = 0; o < 3; o++) {
    for (int c = 0; c < 3; c++) d_Af[S][lh][o * 3 + c] = (float)Ad[o][c];
    d_cf[S][lh][o] = (float)cd[o];
  }

  if (S == 2) {
    // predictor pre-BN u = w4.z + b4 is linear in h2 -> stats from h2 moments
    double mz[3], Amh[3];
    for (int o = 0; o < 3; o++) {
      Amh[o] = Ad[o][0] * m[0] + Ad[o][1] * m[1] + Ad[o][2] * m[2];
      mz[o] = Amh[o] + cd[o];
    }
    double Ezz[3][3];
    for (int o = 0; o < 3; o++)
      for (int p = 0; p < 3; p++) {
        double t = 0.0;
        for (int c = 0; c < 3; c++)
          for (int d = 0; d < 3; d++) t += Ad[o][c] * Ad[p][d] * E[c][d];
        Ezz[o][p] = t + cd[o] * Amh[p] + cd[p] * Amh[o] + cd[o] * cd[p];
      }
    double w4v[3];
    for (int c = 0; c < 3; c++) w4v[c] = (double)W4[head * 3 + c];
    double b4v = (double)b4[head];
    double w4mz = w4v[0] * mz[0] + w4v[1] * mz[1] + w4v[2] * mz[2];
    double mu = w4mz + b4v;
    double eu2 = 0.0;
    for (int c = 0; c < 3; c++)
      for (int d = 0; d < 3; d++) eu2 += w4v[c] * w4v[d] * Ezz[c][d];
    eu2 += 2.0 * b4v * w4mz + b4v * b4v;
    double vu = eu2 - mu * mu;
    double s4 = (double)g4[head] / sqrt(vu + BN_EPS);
    for (int c = 0; c < 3; c++) d_qf[lh][c] = (float)(s4 * w4v[c]);
    d_rf[lh] = (float)(s4 * (b4v - mu) + (double)be4[head]);
  }
}

// ---------------- final pass: z1,z2,p1,p2 per pixel, cosine loss ----------------
__device__ __forceinline__ void head_forward(const float* A1, const float* c1,
                                             const float* A2, const float* c2,
                                             const float* A3, const float* c3,
                                             const float* q, float r,
                                             float x0, float x1, float x2,
                                             float& z0, float& z1, float& z2, float& h4) {
  affine_relu(A1, c1, x0, x1, x2);
  affine_relu(A2, c2, x0, x1, x2);
  z0 = fmaf(A3[0], x0, fmaf(A3[1], x1, fmaf(A3[2], x2, c3[0])));
  z1 = fmaf(A3[3], x0, fmaf(A3[4], x1, fmaf(A3[5], x2, c3[1])));
  z2 = fmaf(A3[6], x0, fmaf(A3[7], x1, fmaf(A3[8], x2, c3[2])));
  float u = fmaf(q[0], z0, fmaf(q[1], z1, fmaf(q[2], z2, r)));
  h4 = fmaxf(u, 0.f);
}

// REV traversal relative to momentsH<2> (forward) -> zig-zag L2 reuse.
__global__ void __launch_bounds__(256) loss_kernel(const float* __restrict__ W5,
                                                   const float* __restrict__ b5) {
  int bid = blockIdx.y * NB4 + blockIdx.x;
  bid = NB4 * NHEADS - 1 - bid;                 // reverse
  int head = bid / NB4, bx = bid % NB4;

  float A1[2][9], c1[2][3], A2[2][9], c2[2][3], A3[2][9], c3[2][3], qv[2][3], rv[2];
  #pragma unroll
  for (int l = 0; l < 2; l++) {
    int lh = l * NHEADS + head;
    #pragma unroll
    for (int k = 0; k < 9; k++) { A1[l][k] = d_Af[0][lh][k]; A2[l][k] = d_Af[1][lh][k]; A3[l][k] = d_Af[2][lh][k]; }
    #pragma unroll
    for (int k = 0; k < 3; k++) { c1[l][k] = d_cf[0][lh][k]; c2[l][k] = d_cf[1][lh][k]; c3[l][k] = d_cf[2][lh][k]; qv[l][k] = d_qf[lh][k]; }
    rv[l] = d_rf[lh];
  }
  float w5v[3], b5v[3];
  #pragma unroll
  for (int o = 0; o < 3; o++) { w5v[o] = W5[head * 3 + o]; b5v[o] = b5[head * 3 + o]; }
  float w55 = w5v[0] * w5v[0] + w5v[1] * w5v[1] + w5v[2] * w5v[2];
  float wb2 = 2.f * (w5v[0] * b5v[0] + w5v[1] * b5v[1] + w5v[2] * b5v[2]);
  float b55 = b5v[0] * b5v[0] + b5v[1] * b5v[1] + b5v[2] * b5v[2];

  float acc = 0.f;
  const int GPB = GROUPS8 / NB4;         // 512
  const int ITER = GPB / 256;            // 2
  int base_g = bx * GPB;

  for (int it = 0; it < ITER; it++) {
    int g  = base_g + it * 256 + threadIdx.x;
    int b  = g >> 14;
    int pg = (g & 16383) << 3;
    size_t po = (size_t)(b * NHEADS + head) * PLANE;
    Pk pk[2][3];
    #pragma unroll
    for (int l = 0; l < 2; l++)
      #pragma unroll
      for (int c = 0; c < 3; c++)
        pk[l][c].u = *(const uint4*)(d_x16[l] + po + c * CHSTRIDE + pg);
    #pragma unroll
    for (int w = 0; w < 4; w++) {
      float2 fa[2][3];
      #pragma unroll
      for (int l = 0; l < 2; l++)
        #pragma unroll
        for (int c = 0; c < 3; c++) fa[l][c] = __half22float2(pk[l][c].h[w]);
      #pragma unroll
      for (int half = 0; half < 2; half++) {
        float xa0 = half ? fa[0][0].y : fa[0][0].x;
        float xa1 = half ? fa[0][1].y : fa[0][1].x;
        float xa2 = half ? fa[0][2].y : fa[0][2].x;
        float xb0 = half ? fa[1][0].y : fa[1][0].x;
        float xb1 = half ? fa[1][1].y : fa[1][1].x;
        float xb2 = half ? fa[1][2].y : fa[1][2].x;
        float z10, z11, z12, h41;
        head_forward(A1[0], c1[0], A2[0], c2[0], A3[0], c3[0], qv[0], rv[0],
                     xa0, xa1, xa2, z10, z11, z12, h41);
        float z20, z21, z22, h42;
        head_forward(A1[1], c1[1], A2[1], c2[1], A3[1], c3[1], qv[1], rv[1],
                     xb0, xb1, xb2, z20, z21, z22, h42);
        // cos(p1, z2): p1 = w5*h41 + b5
        {
          float wz = w5v[0] * z20 + w5v[1] * z21 + w5v[2] * z22;
          float bz = b5v[0] * z20 + b5v[1] * z21 + b5v[2] * z22;
          float dot = fmaf(h41, wz, bz);
          float pp = fmaf(fmaf(w55, h41, wb2), h41, b55);
          float zz = z20 * z20 + z21 * z21 + z22 * z22;
          acc = fmaf(dot, rsqrtf(fmaxf(pp, 1e-16f) * fmaxf(zz, 1e-16f)), acc);
        }
        // cos(p2, z1)
        {
          float wz = w5v[0] * z10 + w5v[1] * z11 + w5v[2] * z12;
          float bz = b5v[0] * z10 + b5v[1] * z11 + b5v[2] * z12;
          float dot = fmaf(h42, wz, bz);
          float pp = fmaf(fmaf(w55, h42, wb2), h42, b55);
          float zz = z10 * z10 + z11 * z11 + z12 * z12;
          acc = fmaf(dot, rsqrtf(fmaxf(pp, 1e-16f) * fmaxf(zz, 1e-16f)), acc);
        }
      }
    }
  }

  #pragma unroll
  for (int o = 16; o > 0; o >>= 1) acc += __shfl_down_sync(0xffffffffu, acc, o);
  __shared__ float red[8];
  int warp = threadIdx.x >> 5, lane = threadIdx.x & 31;
  if (lane == 0) red[warp] = acc;
  __syncthreads();
  if (threadIdx.x == 0) {
    float t = 0.f;
    #pragma unroll
    for (int w = 0; w < 8; w++) t += red[w];
    d_lpart[head][bx] = t;
  }
}

__global__ void __launch_bounds__(256) writeout_kernel(float* out) {
  int t = threadIdx.x;
  double acc = 0.0;
  for (int h = 0; h < NHEADS; h++) acc += (double)d_lpart[h][t];
  __shared__ double red[256];
  red[t] = acc;
  __syncthreads();
  for (int o = 128; o > 0; o >>= 1) {
    if (t < o) red[t] += red[t + o];
    __syncthreads();
  }
  if (t == 0) out[0] = (float)(red[0] * (-0.5 / NPIX_D));
}

// ---------------- launch ----------------
extern "C" void kernel_launch(void* const* d_in, const int* in_sizes, int n_in,
                              void* d_out, int out_size) {
  const float* lat1 = (const float*)d_in[0];
  const float* lat2 = (const float*)d_in[1];
  const float* W1 = (const float*)d_in[2];
  const float* b1 = (const float*)d_in[3];
  const float* g1 = (const float*)d_in[4];
  const float* be1 = (const float*)d_in[5];
  const float* W2 = (const float*)d_in[6];
  const float* b2 = (const float*)d_in[7];
  const float* g2 = (const float*)d_in[8];
  const float* be2 = (const float*)d_in[9];
  const float* W3 = (const float*)d_in[10];
  const float* b3 = (const float*)d_in[11];
  const float* g3 = (const float*)d_in[12];
  const float* be3 = (const float*)d_in[13];
  const float* W4 = (const float*)d_in[14];
  const float* b4 = (const float*)d_in[15];
  const float* g4 = (const float*)d_in[16];
  const float* be4 = (const float*)d_in[17];
  const float* W5 = (const float*)d_in[18];
  const float* b5 = (const float*)d_in[19];

  pass0_kernel<<<dim3(NB0, NLH), 256>>>(lat1, lat2);
  finalize_kernel<0, NB0><<<1, 32>>>(W1, b1, g1, be1, nullptr, nullptr, nullptr, nullptr);
  momentsH_kernel<1, true><<<dim3(NBS, NLH), 256>>>();   // reverse vs pass0 writes
  finalize_kernel<1, NBS><<<1, 32>>>(W2, b2, g2, be2, nullptr, nullptr, nullptr, nullptr);
  momentsH_kernel<2, false><<<dim3(NBS, NLH), 256>>>();  // forward (reverse vs mH1)
  finalize_kernel<2, NBS><<<1, 32>>>(W3, b3, g3, be3, W4, b4, g4, be4);
  loss_kernel<<<dim3(NB4, NHEADS), 256>>>(W5, b5);       // reverse vs mH2
  writeout_kernel<<<1, 256>>>((float*)d_out);
}

// round 4
// speedup vs baseline: 2.2822x; 2.2822x over previous
#include <cuda_runtime.h>
#include <cuda_fp16.h>
#include <math.h>

#define NHEADS   12
#define NLH      24          // (latent, head) pairs
#define CHSTRIDE 131072      // elems between channels within a (b,head) plane
#define PLANE    393216      // elems per (b,head) plane = 3*CHSTRIDE
#define LATELEMS 37748736    // elems per latent
#define NPIX_D   1048576.0   // pixels per head (8 * 131072)
#define GROUPS8  131072      // 8-pixel groups per (latent,head)
#define NB0      128         // blocks per (l,h) for pass0
#define NBS      128         // blocks per (l,h) for fp16 moments passes
#define NB4      256         // blocks per head for loss pass
#define BN_EPS   1e-5

// ---------------- device scratch (no allocation allowed) ----------------
__device__ __align__(16) __half d_x16[2][LATELEMS];   // fp16 staged latents (151MB)
__device__ double d_mom[3][NLH][9];
__device__ float  d_Af[3][NLH][9];
__device__ float  d_cf[3][NLH][3];
__device__ float  d_qf[NLH][3];
__device__ float  d_rf[NLH];
__device__ double d_loss;

// ---------------- helpers ----------------
__global__ void zero_kernel() {
  int t = threadIdx.x;
  double* p = &d_mom[0][0][0];
  for (int i = t; i < 3 * NLH * 9; i += blockDim.x) p[i] = 0.0;
  if (t == 0) d_loss = 0.0;
}

__device__ __forceinline__ void affine_relu(const float* A, const float* c,
                                            float& x0, float& x1, float& x2) {
  float y0 = fmaf(A[0], x0, fmaf(A[1], x1, fmaf(A[2], x2, c[0])));
  float y1 = fmaf(A[3], x0, fmaf(A[4], x1, fmaf(A[5], x2, c[1])));
  float y2 = fmaf(A[6], x0, fmaf(A[7], x1, fmaf(A[8], x2, c[2])));
  x0 = fmaxf(y0, 0.f); x1 = fmaxf(y1, 0.f); x2 = fmaxf(y2, 0.f);
}

__device__ __forceinline__ void mom_acc(float* s, float x0, float x1, float x2) {
  s[0] += x0; s[1] += x1; s[2] += x2;
  s[3] = fmaf(x0, x0, s[3]); s[4] = fmaf(x0, x1, s[4]); s[5] = fmaf(x0, x2, s[5]);
  s[6] = fmaf(x1, x1, s[6]); s[7] = fmaf(x1, x2, s[7]); s[8] = fmaf(x2, x2, s[8]);
}

__device__ __forceinline__ void block_reduce9(float* s, int stage, int lh) {
  #pragma unroll
  for (int k = 0; k < 9; k++)
    #pragma unroll
    for (int o = 16; o > 0; o >>= 1) s[k] += __shfl_down_sync(0xffffffffu, s[k], o);
  __shared__ float red[8][9];
  int warp = threadIdx.x >> 5, lane = threadIdx.x & 31;
  if (lane == 0) {
    #pragma unroll
    for (int k = 0; k < 9; k++) red[warp][k] = s[k];
  }
  __syncthreads();
  if (threadIdx.x < 9) {
    float t = 0.f;
    #pragma unroll
    for (int w = 0; w < 8; w++) t += red[w][threadIdx.x];
    atomicAdd(&d_mom[stage][lh][threadIdx.x], (double)t);
  }
}

union Pk { uint4 u; __half2 h[4]; };

// ---------------- pass 0: fp32 read -> moments of x + fp16 stage-out ----------------
__global__ void __launch_bounds__(256) pass0_kernel(const float* __restrict__ lat1,
                                                    const float* __restrict__ lat2) {
  int lh = blockIdx.y;
  int l = lh / NHEADS, head = lh - l * NHEADS;
  const float* __restrict__ src = l ? lat2 : lat1;
  __half* __restrict__ dst = d_x16[l];

  float s[9];
  #pragma unroll
  for (int k = 0; k < 9; k++) s[k] = 0.f;

  const int GPB = GROUPS8 / NB0;         // 1024
  const int ITER = GPB / 256;            // 4
  int base_g = blockIdx.x * GPB;

  for (int it = 0; it < ITER; it++) {
    int g  = base_g + it * 256 + threadIdx.x;
    int b  = g >> 14;                    // 16384 groups of 8 per channel
    int pg = (g & 16383) << 3;
    size_t po = (size_t)(b * NHEADS + head) * PLANE;
    const float* plane = src + po;
    Pk pk[3];
    #pragma unroll
    for (int c = 0; c < 3; c++) {
      float4 v0 = *(const float4*)(plane + c * CHSTRIDE + pg);
      float4 v1 = *(const float4*)(plane + c * CHSTRIDE + pg + 4);
      pk[c].h[0] = __floats2half2_rn(v0.x, v0.y);
      pk[c].h[1] = __floats2half2_rn(v0.z, v0.w);
      pk[c].h[2] = __floats2half2_rn(v1.x, v1.y);
      pk[c].h[3] = __floats2half2_rn(v1.z, v1.w);
      *(uint4*)(dst + po + c * CHSTRIDE + pg) = pk[c].u;
    }
    // accumulate moments of the *rounded* values (consistent with later passes)
    #pragma unroll
    for (int w = 0; w < 4; w++) {
      float2 f0 = __half22float2(pk[0].h[w]);
      float2 f1 = __half22float2(pk[1].h[w]);
      float2 f2 = __half22float2(pk[2].h[w]);
      mom_acc(s, f0.x, f1.x, f2.x);
      mom_acc(s, f0.y, f1.y, f2.y);
    }
  }
  block_reduce9(s, 0, lh);
}

// ---------------- fp16 moments passes (stage 1: h1, stage 2: h2) ----------------
// REV flips the (lh, block) traversal so this pass starts on the data the
// previous pass touched last (still L2-resident) -> zig-zag L2 reuse.
template <int S, bool REV>
__global__ void __launch_bounds__(256) momentsH_kernel() {
  int bid = blockIdx.y * NBS + blockIdx.x;
  if (REV) bid = NBS * NLH - 1 - bid;
  int lh = bid / NBS, bx = bid % NBS;
  const __half* __restrict__ src = d_x16[lh / NHEADS];
  int head = lh % NHEADS;

  float A1[9], c1[3], A2[9], c2[3];
  #pragma unroll
  for (int k = 0; k < 9; k++) A1[k] = d_Af[0][lh][k];
  #pragma unroll
  for (int k = 0; k < 3; k++) c1[k] = d_cf[0][lh][k];
  if (S >= 2) {
    #pragma unroll
    for (int k = 0; k < 9; k++) A2[k] = d_Af[1][lh][k];
    #pragma unroll
    for (int k = 0; k < 3; k++) c2[k] = d_cf[1][lh][k];
  }

  float s[9];
  #pragma unroll
  for (int k = 0; k < 9; k++) s[k] = 0.f;

  const int GPB = GROUPS8 / NBS;         // 1024
  const int ITER = GPB / 256;            // 4
  int base_g = bx * GPB;

  for (int it = 0; it < ITER; it++) {
    int g  = base_g + it * 256 + threadIdx.x;
    int b  = g >> 14;
    int pg = (g & 16383) << 3;
    size_t po = (size_t)(b * NHEADS + head) * PLANE;
    Pk pk[3];
    #pragma unroll
    for (int c = 0; c < 3; c++) pk[c].u = *(const uint4*)(src + po + c * CHSTRIDE + pg);
    #pragma unroll
    for (int w = 0; w < 4; w++) {
      float2 f0 = __half22float2(pk[0].h[w]);
      float2 f1 = __half22float2(pk[1].h[w]);
      float2 f2 = __half22float2(pk[2].h[w]);
      #pragma unroll
      for (int half = 0; half < 2; half++) {
        float x0 = half ? f0.y : f0.x;
        float x1 = half ? f1.y : f1.x;
        float x2 = half ? f2.y : f2.x;
        affine_relu(A1, c1, x0, x1, x2);
        if (S >= 2) affine_relu(A2, c2, x0, x1, x2);
        mom_acc(s, x0, x1, x2);
      }
    }
  }
  block_reduce9(s, S, lh);
}

// ---------------- finalize: fold conv+BN into affine from stage-S moments ----------------
template <int S>
__global__ void finalize_kernel(const float* __restrict__ W, const float* __restrict__ bb,
                                const float* __restrict__ g, const float* __restrict__ be,
                                const float* __restrict__ W4, const float* __restrict__ b4,
                                const float* __restrict__ g4, const float* __restrict__ be4) {
  int lh = threadIdx.x;
  if (lh >= NLH) return;
  int head = lh % NHEADS;
  const double inv = 1.0 / NPIX_D;
  const double* M = d_mom[S][lh];
  double m[3], E[3][3];
  m[0] = M[0] * inv; m[1] = M[1] * inv; m[2] = M[2] * inv;
  E[0][0] = M[3] * inv; E[0][1] = E[1][0] = M[4] * inv; E[0][2] = E[2][0] = M[5] * inv;
  E[1][1] = M[6] * inv; E[1][2] = E[2][1] = M[7] * inv; E[2][2] = M[8] * inv;

  double Wl[3][3], bl[3];
  for (int o = 0; o < 3; o++) {
    for (int c = 0; c < 3; c++) Wl[o][c] = (double)W[head * 9 + o * 3 + c];
    bl[o] = (double)bb[head * 3 + o];
  }

  double Ad[3][3], cd[3];
  for (int o = 0; o < 3; o++) {
    double wm = Wl[o][0] * m[0] + Wl[o][1] * m[1] + Wl[o][2] * m[2];
    double mo = wm + bl[o];
    double e2 = 0.0;
    for (int c = 0; c < 3; c++)
      for (int d = 0; d < 3; d++) e2 += Wl[o][c] * Wl[o][d] * E[c][d];
    e2 += 2.0 * bl[o] * wm + bl[o] * bl[o];
    double v = e2 - mo * mo;
    double sc = (double)g[head * 3 + o] / sqrt(v + BN_EPS);
    for (int c = 0; c < 3; c++) Ad[o][c] = sc * Wl[o][c];
    cd[o] = sc * (bl[o] - mo) + (double)be[head * 3 + o];
  }
  for (int o = 0; o < 3; o++) {
    for (int c = 0; c < 3; c++) d_Af[S][lh][o * 3 + c] = (float)Ad[o][c];
    d_cf[S][lh][o] = (float)cd[o];
  }

  if (S == 2) {
    // predictor pre-BN u = w4.z + b4 is linear in h2 -> stats from h2 moments
    double mz[3], Amh[3];
    for (int o = 0; o < 3; o++) {
      Amh[o] = Ad[o][0] * m[0] + Ad[o][1] * m[1] + Ad[o][2] * m[2];
      mz[o] = Amh[o] + cd[o];
    }
    double Ezz[3][3];
    for (int o = 0; o < 3; o++)
      for (int p = 0; p < 3; p++) {
        double t = 0.0;
        for (int c = 0; c < 3; c++)
          for (int d = 0; d < 3; d++) t += Ad[o][c] * Ad[p][d] * E[c][d];
        Ezz[o][p] = t + cd[o] * Amh[p] + cd[p] * Amh[o] + cd[o] * cd[p];
      }
    double w4v[3];
    for (int c = 0; c < 3; c++) w4v[c] = (double)W4[head * 3 + c];
    double b4v = (double)b4[head];
    double w4mz = w4v[0] * mz[0] + w4v[1] * mz[1] + w4v[2] * mz[2];
    double mu = w4mz + b4v;
    double eu2 = 0.0;
    for (int c = 0; c < 3; c++)
      for (int d = 0; d < 3; d++) eu2 += w4v[c] * w4v[d] * Ezz[c][d];
    eu2 += 2.0 * b4v * w4mz + b4v * b4v;
    double vu = eu2 - mu * mu;
    double s4 = (double)g4[head] / sqrt(vu + BN_EPS);
    for (int c = 0; c < 3; c++) d_qf[lh][c] = (float)(s4 * w4v[c]);
    d_rf[lh] = (float)(s4 * (b4v - mu) + (double)be4[head]);
  }
}

// ---------------- final pass: z1,z2,p1,p2 per pixel, cosine loss ----------------
__device__ __forceinline__ void head_forward(const float* A1, const float* c1,
                                             const float* A2, const float* c2,
                                             const float* A3, const float* c3,
                                             const float* q, float r,
                                             float x0, float x1, float x2,
                                             float& z0, float& z1, float& z2, float& h4) {
  affine_relu(A1, c1, x0, x1, x2);
  affine_relu(A2, c2, x0, x1, x2);
  z0 = fmaf(A3[0], x0, fmaf(A3[1], x1, fmaf(A3[2], x2, c3[0])));
  z1 = fmaf(A3[3], x0, fmaf(A3[4], x1, fmaf(A3[5], x2, c3[1])));
  z2 = fmaf(A3[6], x0, fmaf(A3[7], x1, fmaf(A3[8], x2, c3[2])));
  float u = fmaf(q[0], z0, fmaf(q[1], z1, fmaf(q[2], z2, r)));
  h4 = fmaxf(u, 0.f);
}

// Reverse traversal relative to momentsH<2> (forward) -> zig-zag L2 reuse.
__global__ void __launch_bounds__(256) loss_kernel(const float* __restrict__ W5,
                                                   const float* __restrict__ b5) {
  int bid = blockIdx.y * NB4 + blockIdx.x;
  bid = NB4 * NHEADS - 1 - bid;                 // reverse
  int head = bid / NB4, bx = bid % NB4;

  float A1[2][9], c1[2][3], A2[2][9], c2[2][3], A3[2][9], c3[2][3], qv[2][3], rv[2];
  #pragma unroll
  for (int l = 0; l < 2; l++) {
    int lh = l * NHEADS + head;
    #pragma unroll
    for (int k = 0; k < 9; k++) { A1[l][k] = d_Af[0][lh][k]; A2[l][k] = d_Af[1][lh][k]; A3[l][k] = d_Af[2][lh][k]; }
    #pragma unroll
    for (int k = 0; k < 3; k++) { c1[l][k] = d_cf[0][lh][k]; c2[l][k] = d_cf[1][lh][k]; c3[l][k] = d_cf[2][lh][k]; qv[l][k] = d_qf[lh][k]; }
    rv[l] = d_rf[lh];
  }
  float w5v[3], b5v[3];
  #pragma unroll
  for (int o = 0; o < 3; o++) { w5v[o] = W5[head * 3 + o]; b5v[o] = b5[head * 3 + o]; }
  float w55 = w5v[0] * w5v[0] + w5v[1] * w5v[1] + w5v[2] * w5v[2];
  float wb2 = 2.f * (w5v[0] * b5v[0] + w5v[1] * b5v[1] + w5v[2] * b5v[2]);
  float b55 = b5v[0] * b5v[0] + b5v[1] * b5v[1] + b5v[2] * b5v[2];

  float acc = 0.f;
  const int GPB = GROUPS8 / NB4;         // 512
  const int ITER = GPB / 256;            // 2
  int base_g = bx * GPB;

  for (int it = 0; it < ITER; it++) {
    int g  = base_g + it * 256 + threadIdx.x;
    int b  = g >> 14;
    int pg = (g & 16383) << 3;
    size_t po = (size_t)(b * NHEADS + head) * PLANE;
    Pk pk[2][3];
    #pragma unroll
    for (int l = 0; l < 2; l++)
      #pragma unroll
      for (int c = 0; c < 3; c++)
        pk[l][c].u = *(const uint4*)(d_x16[l] + po + c * CHSTRIDE + pg);
    #pragma unroll
    for (int w = 0; w < 4; w++) {
      float2 fa[2][3];
      #pragma unroll
      for (int l = 0; l < 2; l++)
        #pragma unroll
        for (int c = 0; c < 3; c++) fa[l][c] = __half22float2(pk[l][c].h[w]);
      #pragma unroll
      for (int half = 0; half < 2; half++) {
        float xa0 = half ? fa[0][0].y : fa[0][0].x;
        float xa1 = half ? fa[0][1].y : fa[0][1].x;
        float xa2 = half ? fa[0][2].y : fa[0][2].x;
        float xb0 = half ? fa[1][0].y : fa[1][0].x;
        float xb1 = half ? fa[1][1].y : fa[1][1].x;
        float xb2 = half ? fa[1][2].y : fa[1][2].x;
        float z10, z11, z12, h41;
        head_forward(A1[0], c1[0], A2[0], c2[0], A3[0], c3[0], qv[0], rv[0],
                     xa0, xa1, xa2, z10, z11, z12, h41);
        float z20, z21, z22, h42;
        head_forward(A1[1], c1[1], A2[1], c2[1], A3[1], c3[1], qv[1], rv[1],
                     xb0, xb1, xb2, z20, z21, z22, h42);
        // cos(p1, z2): p1 = w5*h41 + b5
        {
          float wz = w5v[0] * z20 + w5v[1] * z21 + w5v[2] * z22;
          float bz = b5v[0] * z20 + b5v[1] * z21 + b5v[2] * z22;
          float dot = fmaf(h41, wz, bz);
          float pp = fmaf(fmaf(w55, h41, wb2), h41, b55);
          float zz = z20 * z20 + z21 * z21 + z22 * z22;
          acc = fmaf(dot, rsqrtf(fmaxf(pp, 1e-16f) * fmaxf(zz, 1e-16f)), acc);
        }
        // cos(p2, z1)
        {
          float wz = w5v[0] * z10 + w5v[1] * z11 + w5v[2] * z12;
          float bz = b5v[0] * z10 + b5v[1] * z11 + b5v[2] * z12;
          float dot = fmaf(h42, wz, bz);
          float pp = fmaf(fmaf(w55, h42, wb2), h42, b55);
          float zz = z10 * z10 + z11 * z11 + z12 * z12;
          acc = fmaf(dot, rsqrtf(fmaxf(pp, 1e-16f) * fmaxf(zz, 1e-16f)), acc);
        }
      }
    }
  }

  #pragma unroll
  for (int o = 16; o > 0; o >>= 1) acc += __shfl_down_sync(0xffffffffu, acc, o);
  __shared__ float red[8];
  int warp = threadIdx.x >> 5, lane = threadIdx.x & 31;
  if (lane == 0) red[warp] = acc;
  __syncthreads();
  if (threadIdx.x == 0) {
    float t = 0.f;
    #pragma unroll
    for (int w = 0; w < 8; w++) t += red[w];
    atomicAdd(&d_loss, (double)t);
  }
}

__global__ void writeout_kernel(float* out) {
  out[0] = (float)(d_loss * (-0.5 / NPIX_D));
}

// ---------------- launch ----------------
extern "C" void kernel_launch(void* const* d_in, const int* in_sizes, int n_in,
                              void* d_out, int out_size) {
  const float* lat1 = (const float*)d_in[0];
  const float* lat2 = (const float*)d_in[1];
  const float* W1 = (const float*)d_in[2];
  const float* b1 = (const float*)d_in[3];
  const float* g1 = (const float*)d_in[4];
  const float* be1 = (const float*)d_in[5];
  const float* W2 = (const float*)d_in[6];
  const float* b2 = (const float*)d_in[7];
  const float* g2 = (const float*)d_in[8];
  const float* be2 = (const float*)d_in[9];
  const float* W3 = (const float*)d_in[10];
  const float* b3 = (const float*)d_in[11];
  const float* g3 = (const float*)d_in[12];
  const float* be3 = (const float*)d_in[13];
  const float* W4 = (const float*)d_in[14];
  const float* b4 = (const float*)d_in[15];
  const float* g4 = (const float*)d_in[16];
  const float* be4 = (const float*)d_in[17];
  const float* W5 = (const float*)d_in[18];
  const float* b5 = (const float*)d_in[19];

  zero_kernel<<<1, 256>>>();
  pass0_kernel<<<dim3(NB0, NLH), 256>>>(lat1, lat2);
  finalize_kernel<0><<<1, 32>>>(W1, b1, g1, be1, nullptr, nullptr, nullptr, nullptr);
  momentsH_kernel<1, true><<<dim3(NBS, NLH), 256>>>();   // reverse vs pass0 writes
  finalize_kernel<1><<<1, 32>>>(W2, b2, g2, be2, nullptr, nullptr, nullptr, nullptr);
  momentsH_kernel<2, false><<<dim3(NBS, NLH), 256>>>();  // forward (reverse vs mH1)
  finalize_kernel<2><<<1, 32>>>(W3, b3, g3, be3, W4, b4, g4, be4);
  loss_kernel<<<dim3(NB4, NHEADS), 256>>>(W5, b5);       // reverse vs mH2
  writeout_kernel<<<1, 1>>>((float*)d_out);
}

// round 5
// speedup vs baseline: 2.4158x; 1.0585x over previous
#include <cuda_runtime.h>
#include <cuda_fp16.h>
#include <math.h>

#define NHEADS   12
#define NLH      24          // (latent, head) pairs
#define CHSTRIDE 131072      // elems between channels within a (b,head) plane
#define PLANE    393216      // elems per (b,head) plane = 3*CHSTRIDE
#define LATELEMS 37748736    // elems per latent
#define NPIX_D   1048576.0   // pixels per head (8 * 131072)
#define GROUPS8  131072      // 8-pixel groups per (latent,head)
#define NB0      128         // blocks per (l,h) for pass0
#define NBS      128         // blocks per (l,h) for fp16 moments passes
#define NB4      256         // blocks per head for loss pass
#define BN_EPS   1e-5

// ---------------- device scratch (no allocation allowed) ----------------
__device__ __align__(16) __half d_x16[2][LATELEMS];   // fp16 staged latents (151MB)
__device__ double d_mom[3][NLH][9];
__device__ float  d_Af[3][NLH][9];
__device__ float  d_cf[3][NLH][3];
__device__ float  d_qf[NLH][3];
__device__ float  d_rf[NLH];
__device__ double d_loss;

// ---------------- helpers ----------------
__global__ void zero_kernel() {
  int t = threadIdx.x;
  double* p = &d_mom[0][0][0];
  for (int i = t; i < 3 * NLH * 9; i += blockDim.x) p[i] = 0.0;
  if (t == 0) d_loss = 0.0;
}

__device__ __forceinline__ void affine_relu_h2(const __half2* A, const __half2* c,
                                               __half2& x0, __half2& x1, __half2& x2) {
  __half2 y0 = __hfma2(A[0], x0, __hfma2(A[1], x1, __hfma2(A[2], x2, c[0])));
  __half2 y1 = __hfma2(A[3], x0, __hfma2(A[4], x1, __hfma2(A[5], x2, c[1])));
  __half2 y2 = __hfma2(A[6], x0, __hfma2(A[7], x1, __hfma2(A[8], x2, c[2])));
  const __half2 zz = __float2half2_rn(0.f);
  x0 = __hmax2(y0, zz); x1 = __hmax2(y1, zz); x2 = __hmax2(y2, zz);
}

__device__ __forceinline__ void mom_acc_h2(__half2* s, __half2 x0, __half2 x1, __half2 x2) {
  s[0] = __hadd2(s[0], x0); s[1] = __hadd2(s[1], x1); s[2] = __hadd2(s[2], x2);
  s[3] = __hfma2(x0, x0, s[3]); s[4] = __hfma2(x0, x1, s[4]); s[5] = __hfma2(x0, x2, s[5]);
  s[6] = __hfma2(x1, x1, s[6]); s[7] = __hfma2(x1, x2, s[7]); s[8] = __hfma2(x2, x2, s[8]);
}

__device__ __forceinline__ void block_reduce9_h2(__half2* sh, int stage, int lh) {
  float s[9];
  #pragma unroll
  for (int k = 0; k < 9; k++) s[k] = __low2float(sh[k]) + __high2float(sh[k]);
  #pragma unroll
  for (int k = 0; k < 9; k++)
    #pragma unroll
    for (int o = 16; o > 0; o >>= 1) s[k] += __shfl_down_sync(0xffffffffu, s[k], o);
  __shared__ float red[8][9];
  int warp = threadIdx.x >> 5, lane = threadIdx.x & 31;
  if (lane == 0) {
    #pragma unroll
    for (int k = 0; k < 9; k++) red[warp][k] = s[k];
  }
  __syncthreads();
  if (threadIdx.x < 9) {
    float t = 0.f;
    #pragma unroll
    for (int w = 0; w < 8; w++) t += red[w][threadIdx.x];
    atomicAdd(&d_mom[stage][lh][threadIdx.x], (double)t);
  }
}

union Pk { uint4 u; __half2 h[4]; };

// ---------------- pass 0: fp32 read -> moments of x + fp16 stage-out ----------------
__global__ void __launch_bounds__(256) pass0_kernel(const float* __restrict__ lat1,
                                                    const float* __restrict__ lat2) {
  int lh = blockIdx.y;
  int l = lh / NHEADS, head = lh - l * NHEADS;
  const float* __restrict__ src = l ? lat2 : lat1;
  __half* __restrict__ dst = d_x16[l];

  __half2 s[9];
  #pragma unroll
  for (int k = 0; k < 9; k++) s[k] = __float2half2_rn(0.f);

  const int GPB = GROUPS8 / NB0;         // 1024
  const int ITER = GPB / 256;            // 4
  int base_g = blockIdx.x * GPB;

  for (int it = 0; it < ITER; it++) {
    int g  = base_g + it * 256 + threadIdx.x;
    int b  = g >> 14;                    // 16384 groups of 8 per channel
    int pg = (g & 16383) << 3;
    size_t po = (size_t)(b * NHEADS + head) * PLANE;
    const float* plane = src + po;
    Pk pk[3];
    #pragma unroll
    for (int c = 0; c < 3; c++) {
      float4 v0 = *(const float4*)(plane + c * CHSTRIDE + pg);
      float4 v1 = *(const float4*)(plane + c * CHSTRIDE + pg + 4);
      pk[c].h[0] = __floats2half2_rn(v0.x, v0.y);
      pk[c].h[1] = __floats2half2_rn(v0.z, v0.w);
      pk[c].h[2] = __floats2half2_rn(v1.x, v1.y);
      pk[c].h[3] = __floats2half2_rn(v1.z, v1.w);
      *(uint4*)(dst + po + c * CHSTRIDE + pg) = pk[c].u;
    }
    #pragma unroll
    for (int w = 0; w < 4; w++) mom_acc_h2(s, pk[0].h[w], pk[1].h[w], pk[2].h[w]);
  }
  block_reduce9_h2(s, 0, lh);
}

// ---------------- fp16 moments passes (stage 1: h1, stage 2: h2) ----------------
// REV flips the (lh, block) traversal so this pass starts on the data the
// previous pass touched last (still L2-resident) -> zig-zag L2 reuse.
template <int S, bool REV>
__global__ void __launch_bounds__(256) momentsH_kernel() {
  int bid = blockIdx.y * NBS + blockIdx.x;
  if (REV) bid = NBS * NLH - 1 - bid;
  int lh = bid / NBS, bx = bid % NBS;
  const __half* __restrict__ src = d_x16[lh / NHEADS];
  int head = lh % NHEADS;

  __half2 A1[9], c1[3], A2[9], c2[3];
  #pragma unroll
  for (int k = 0; k < 9; k++) A1[k] = __float2half2_rn(d_Af[0][lh][k]);
  #pragma unroll
  for (int k = 0; k < 3; k++) c1[k] = __float2half2_rn(d_cf[0][lh][k]);
  if (S >= 2) {
    #pragma unroll
    for (int k = 0; k < 9; k++) A2[k] = __float2half2_rn(d_Af[1][lh][k]);
    #pragma unroll
    for (int k = 0; k < 3; k++) c2[k] = __float2half2_rn(d_cf[1][lh][k]);
  }

  __half2 s[9];
  #pragma unroll
  for (int k = 0; k < 9; k++) s[k] = __float2half2_rn(0.f);

  const int GPB = GROUPS8 / NBS;         // 1024
  const int ITER = GPB / 256;            // 4
  int base_g = bx * GPB;

  for (int it = 0; it < ITER; it++) {
    int g  = base_g + it * 256 + threadIdx.x;
    int b  = g >> 14;
    int pg = (g & 16383) << 3;
    size_t po = (size_t)(b * NHEADS + head) * PLANE;
    Pk pk[3];
    #pragma unroll
    for (int c = 0; c < 3; c++) pk[c].u = *(const uint4*)(src + po + c * CHSTRIDE + pg);
    #pragma unroll
    for (int w = 0; w < 4; w++) {
      __half2 x0 = pk[0].h[w], x1 = pk[1].h[w], x2 = pk[2].h[w];
      affine_relu_h2(A1, c1, x0, x1, x2);
      if (S >= 2) affine_relu_h2(A2, c2, x0, x1, x2);
      mom_acc_h2(s, x0, x1, x2);
    }
  }
  block_reduce9_h2(s, S, lh);
}

// ---------------- finalize: fold conv+BN into affine from stage-S moments ----------------
template <int S>
__global__ void finalize_kernel(const float* __restrict__ W, const float* __restrict__ bb,
                                const float* __restrict__ g, const float* __restrict__ be,
                                const float* __restrict__ W4, const float* __restrict__ b4,
                                const float* __restrict__ g4, const float* __restrict__ be4) {
  int lh = threadIdx.x;
  if (lh >= NLH) return;
  int head = lh % NHEADS;
  const double inv = 1.0 / NPIX_D;
  const double* M = d_mom[S][lh];
  double m[3], E[3][3];
  m[0] = M[0] * inv; m[1] = M[1] * inv; m[2] = M[2] * inv;
  E[0][0] = M[3] * inv; E[0][1] = E[1][0] = M[4] * inv; E[0][2] = E[2][0] = M[5] * inv;
  E[1][1] = M[6] * inv; E[1][2] = E[2][1] = M[7] * inv; E[2][2] = M[8] * inv;

  double Wl[3][3], bl[3];
  for (int o = 0; o < 3; o++) {
    for (int c = 0; c < 3; c++) Wl[o][c] = (double)W[head * 9 + o * 3 + c];
    bl[o] = (double)bb[head * 3 + o];
  }

  double Ad[3][3], cd[3];
  for (int o = 0; o < 3; o++) {
    double wm = Wl[o][0] * m[0] + Wl[o][1] * m[1] + Wl[o][2] * m[2];
    double mo = wm + bl[o];
    double e2 = 0.0;
    for (int c = 0; c < 3; c++)
      for (int d = 0; d < 3; d++) e2 += Wl[o][c] * Wl[o][d] * E[c][d];
    e2 += 2.0 * bl[o] * wm + bl[o] * bl[o];
    double v = e2 - mo * mo;
    double sc = (double)g[head * 3 + o] / sqrt(v + BN_EPS);
    for (int c = 0; c < 3; c++) Ad[o][c] = sc * Wl[o][c];
    cd[o] = sc * (bl[o] - mo) + (double)be[head * 3 + o];
  }
  for (int o = 0; o < 3; o++) {
    for (int c = 0; c < 3; c++) d_Af[S][lh][o * 3 + c] = (float)Ad[o][c];
    d_cf[S][lh][o] = (float)cd[o];
  }

  if (S == 2) {
    // predictor pre-BN u = w4.z + b4 is linear in h2 -> stats from h2 moments
    double mz[3], Amh[3];
    for (int o = 0; o < 3; o++) {
      Amh[o] = Ad[o][0] * m[0] + Ad[o][1] * m[1] + Ad[o][2] * m[2];
      mz[o] = Amh[o] + cd[o];
    }
    double Ezz[3][3];
    for (int o = 0; o < 3; o++)
      for (int p = 0; p < 3; p++) {
        double t = 0.0;
        for (int c = 0; c < 3; c++)
          for (int d = 0; d < 3; d++) t += Ad[o][c] * Ad[p][d] * E[c][d];
        Ezz[o][p] = t + cd[o] * Amh[p] + cd[p] * Amh[o] + cd[o] * cd[p];
      }
    double w4v[3];
    for (int c = 0; c < 3; c++) w4v[c] = (double)W4[head * 3 + c];
    double b4v = (double)b4[head];
    double w4mz = w4v[0] * mz[0] + w4v[1] * mz[1] + w4v[2] * mz[2];
    double mu = w4mz + b4v;
    double eu2 = 0.0;
    for (int c = 0; c < 3; c++)
      for (int d = 0; d < 3; d++) eu2 += w4v[c] * w4v[d] * Ezz[c][d];
    eu2 += 2.0 * b4v * w4mz + b4v * b4v;
    double vu = eu2 - mu * mu;
    double s4 = (double)g4[head] / sqrt(vu + BN_EPS);
    for (int c = 0; c < 3; c++) d_qf[lh][c] = (float)(s4 * w4v[c]);
    d_rf[lh] = (float)(s4 * (b4v - mu) + (double)be4[head]);
  }
}

// ---------------- final pass: z1,z2,p1,p2 per pixel, cosine loss (half2) -------
// Reverse traversal relative to momentsH<2> (forward) -> zig-zag L2 reuse.
__global__ void __launch_bounds__(256) loss_kernel(const float* __restrict__ W5,
                                                   const float* __restrict__ b5) {
  int bid = blockIdx.y * NB4 + blockIdx.x;
  bid = NB4 * NHEADS - 1 - bid;                 // reverse
  int head = bid / NB4, bx = bid % NB4;

  __half2 A1[2][9], c1[2][3], A2[2][9], c2[2][3], A3[2][9], c3[2][3], qv[2][3], rv[2];
  #pragma unroll
  for (int l = 0; l < 2; l++) {
    int lh = l * NHEADS + head;
    #pragma unroll
    for (int k = 0; k < 9; k++) {
      A1[l][k] = __float2half2_rn(d_Af[0][lh][k]);
      A2[l][k] = __float2half2_rn(d_Af[1][lh][k]);
      A3[l][k] = __float2half2_rn(d_Af[2][lh][k]);
    }
    #pragma unroll
    for (int k = 0; k < 3; k++) {
      c1[l][k] = __float2half2_rn(d_cf[0][lh][k]);
      c2[l][k] = __float2half2_rn(d_cf[1][lh][k]);
      c3[l][k] = __float2half2_rn(d_cf[2][lh][k]);
      qv[l][k] = __float2half2_rn(d_qf[lh][k]);
    }
    rv[l] = __float2half2_rn(d_rf[lh]);
  }
  float w5f[3], b5f[3];
  #pragma unroll
  for (int o = 0; o < 3; o++) { w5f[o] = W5[head * 3 + o]; b5f[o] = b5[head * 3 + o]; }
  __half2 w5h[3], b5h[3];
  #pragma unroll
  for (int o = 0; o < 3; o++) { w5h[o] = __float2half2_rn(w5f[o]); b5h[o] = __float2half2_rn(b5f[o]); }
  __half2 w55 = __float2half2_rn(w5f[0]*w5f[0] + w5f[1]*w5f[1] + w5f[2]*w5f[2]);
  __half2 wb2 = __float2half2_rn(2.f*(w5f[0]*b5f[0] + w5f[1]*b5f[1] + w5f[2]*b5f[2]));
  __half2 b55 = __float2half2_rn(b5f[0]*b5f[0] + b5f[1]*b5f[1] + b5f[2]*b5f[2]);

  float acc = 0.f;
  const int GPB = GROUPS8 / NB4;         // 512
  const int ITER = GPB / 256;            // 2
  int base_g = bx * GPB;

  for (int it = 0; it < ITER; it++) {
    int g  = base_g + it * 256 + threadIdx.x;
    int b  = g >> 14;
    int pg = (g & 16383) << 3;
    size_t po = (size_t)(b * NHEADS + head) * PLANE;
    Pk pk[2][3];
    #pragma unroll
    for (int l = 0; l < 2; l++)
      #pragma unroll
      for (int c = 0; c < 3; c++)
        pk[l][c].u = *(const uint4*)(d_x16[l] + po + c * CHSTRIDE + pg);
    #pragma unroll
    for (int w = 0; w < 4; w++) {
      __half2 z[2][3], h4[2];
      #pragma unroll
      for (int l = 0; l < 2; l++) {
        __half2 x0 = pk[l][0].h[w], x1 = pk[l][1].h[w], x2 = pk[l][2].h[w];
        affine_relu_h2(A1[l], c1[l], x0, x1, x2);
        affine_relu_h2(A2[l], c2[l], x0, x1, x2);
        z[l][0] = __hfma2(A3[l][0], x0, __hfma2(A3[l][1], x1, __hfma2(A3[l][2], x2, c3[l][0])));
        z[l][1] = __hfma2(A3[l][3], x0, __hfma2(A3[l][4], x1, __hfma2(A3[l][5], x2, c3[l][1])));
        z[l][2] = __hfma2(A3[l][6], x0, __hfma2(A3[l][7], x1, __hfma2(A3[l][8], x2, c3[l][2])));
        __half2 u = __hfma2(qv[l][0], z[l][0], __hfma2(qv[l][1], z[l][1], __hfma2(qv[l][2], z[l][2], rv[l])));
        h4[l] = __hmax2(u, __float2half2_rn(0.f));
      }
      // two symmetric cosine terms: (h4[0] vs z[1]) and (h4[1] vs z[0])
      #pragma unroll
      for (int t = 0; t < 2; t++) {
        const __half2* zz_ = z[1 - t];
        __half2 hh = h4[t];
        __half2 wz = __hfma2(w5h[0], zz_[0], __hfma2(w5h[1], zz_[1], __hmul2(w5h[2], zz_[2])));
        __half2 bz = __hfma2(b5h[0], zz_[0], __hfma2(b5h[1], zz_[1], __hmul2(b5h[2], zz_[2])));
        __half2 dot = __hfma2(hh, wz, bz);
        __half2 pp  = __hfma2(__hfma2(w55, hh, wb2), hh, b55);
        __half2 zn  = __hfma2(zz_[0], zz_[0], __hfma2(zz_[1], zz_[1], __hmul2(zz_[2], zz_[2])));
        __half2 arg = __hmul2(pp, zn);
        float a0 = fmaxf(__low2float(arg), 1e-12f);
        float a1 = fmaxf(__high2float(arg), 1e-12f);
        acc = fmaf(__low2float(dot),  rsqrtf(a0), acc);
        acc = fmaf(__high2float(dot), rsqrtf(a1), acc);
      }
    }
  }

  #pragma unroll
  for (int o = 16; o > 0; o >>= 1) acc += __shfl_down_sync(0xffffffffu, acc, o);
  __shared__ float red[8];
  int warp = threadIdx.x >> 5, lane = threadIdx.x & 31;
  if (lane == 0) red[warp] = acc;
  __syncthreads();
  if (threadIdx.x == 0) {
    float t = 0.f;
    #pragma unroll
    for (int w = 0; w < 8; w++) t += red[w];
    atomicAdd(&d_loss, (double)t);
  }
}

__global__ void writeout_kernel(float* out) {
  out[0] = (float)(d_loss * (-0.5 / NPIX_D));
}

// ---------------- launch ----------------
extern "C" void kernel_launch(void* const* d_in, const int* in_sizes, int n_in,
                              void* d_out, int out_size) {
  const float* lat1 = (const float*)d_in[0];
  const float* lat2 = (const float*)d_in[1];
  const float* W1 = (const float*)d_in[2];
  const float* b1 = (const float*)d_in[3];
  const float* g1 = (const float*)d_in[4];
  const float* be1 = (const float*)d_in[5];
  const float* W2 = (const float*)d_in[6];
  const float* b2 = (const float*)d_in[7];
  const float* g2 = (const float*)d_in[8];
  const float* be2 = (const float*)d_in[9];
  const float* W3 = (const float*)d_in[10];
  const float* b3 = (const float*)d_in[11];
  const float* g3 = (const float*)d_in[12];
  const float* be3 = (const float*)d_in[13];
  const float* W4 = (const float*)d_in[14];
  const float* b4 = (const float*)d_in[15];
  const float* g4 = (const float*)d_in[16];
  const float* be4 = (const float*)d_in[17];
  const float* W5 = (const float*)d_in[18];
  const float* b5 = (const float*)d_in[19];

  zero_kernel<<<1, 256>>>();
  pass0_kernel<<<dim3(NB0, NLH), 256>>>(lat1, lat2);
  finalize_kernel<0><<<1, 32>>>(W1, b1, g1, be1, nullptr, nullptr, nullptr, nullptr);
  momentsH_kernel<1, true><<<dim3(NBS, NLH), 256>>>();   // reverse vs pass0 writes
  finalize_kernel<1><<<1, 32>>>(W2, b2, g2, be2, nullptr, nullptr, nullptr, nullptr);
  momentsH_kernel<2, false><<<dim3(NBS, NLH), 256>>>();  // forward (reverse vs mH1)
  finalize_kernel<2><<<1, 32>>>(W3, b3, g3, be3, W4, b4, g4, be4);
  loss_kernel<<<dim3(NB4, NHEADS), 256>>>(W5, b5);       // reverse vs mH2
  writeout_kernel<<<1, 1>>>((float*)d_out);
}